// round 1
// baseline (speedup 1.0000x reference)
#include <cuda_runtime.h>
#include <math.h>

#define TT 8192
#define IN_DIM 2048
#define OUT_DIM 2048
#define PROJ 512
#define NE 8
#define NSLOT (TT * 2)
#define PADROWS (NSLOT + NE * 64)   // 16896
#define MAXTILES (PADROWS / 64)     // 264

// ---------------- scratch (device globals; no allocations) ----------------
__device__ int   g_route_e[NSLOT];
__device__ float g_route_w[NSLOT];
__device__ int   g_bucket_slot[PADROWS];
__device__ int   g_pos[NSLOT];
__device__ int   g_tile_expert[MAXTILES];
__device__ int   g_tile_rowbase[MAXTILES];
__device__ float g_H[(size_t)PADROWS * PROJ];      // ~34.6 MB
__device__ float g_Y[(size_t)PADROWS * OUT_DIM];   // ~138 MB

__device__ __forceinline__ float gelu_f(float v) {
    const float c = 0.7978845608028654f;  // sqrt(2/pi)
    float inner = c * (v + 0.044715f * v * v * v);
    return 0.5f * v * (1.0f + tanhf(inner));
}

// ---------------- 1. gating: logits -> softmax -> top2 ----------------
__global__ __launch_bounds__(256) void gating_kernel(
    const float* __restrict__ x, const float* __restrict__ gw,
    const float* __restrict__ gb) {
    int warp = threadIdx.x >> 5, lane = threadIdx.x & 31;
    int t = blockIdx.x * 8 + warp;
    const float* xr = x + (size_t)t * IN_DIM;
    float acc[8] = {0.f, 0.f, 0.f, 0.f, 0.f, 0.f, 0.f, 0.f};
    for (int i = lane; i < IN_DIM; i += 32) {
        float xv = xr[i];
        const float4* g4 = (const float4*)(gw + (size_t)i * NE);
        float4 g0 = g4[0], g1 = g4[1];
        acc[0] += xv * g0.x; acc[1] += xv * g0.y;
        acc[2] += xv * g0.z; acc[3] += xv * g0.w;
        acc[4] += xv * g1.x; acc[5] += xv * g1.y;
        acc[6] += xv * g1.z; acc[7] += xv * g1.w;
    }
#pragma unroll
    for (int o = 16; o > 0; o >>= 1)
#pragma unroll
        for (int e = 0; e < 8; e++)
            acc[e] += __shfl_xor_sync(0xffffffffu, acc[e], o);
    if (lane == 0) {
        const float INV = 0.022097086912079608f;  // 1/sqrt(2048)
        float l[8], m = -1e30f;
#pragma unroll
        for (int e = 0; e < 8; e++) {
            l[e] = (acc[e] + gb[e]) * INV;
            m = fmaxf(m, l[e]);
        }
        float p[8], s = 0.f;
#pragma unroll
        for (int e = 0; e < 8; e++) { p[e] = expf(l[e] - m); s += p[e]; }
        int i1 = 0;
#pragma unroll
        for (int e = 1; e < 8; e++) if (l[e] > l[i1]) i1 = e;
        int i2 = (i1 == 0) ? 1 : 0;
#pragma unroll
        for (int e = 0; e < 8; e++) if (e != i1 && l[e] > l[i2]) i2 = e;
        float inv_s = 1.f / s;
        g_route_e[2 * t]     = i1; g_route_w[2 * t]     = p[i1] * inv_s;
        g_route_e[2 * t + 1] = i2; g_route_w[2 * t + 1] = p[i2] * inv_s;
    }
}

// ---------------- 2. deterministic bucketing (stable counting sort) ----------------
__global__ __launch_bounds__(256) void bucket_kernel() {
    __shared__ int hist[256][8];
    __shared__ int offs[256][8];
    __shared__ int tot[8];
    __shared__ int base[8];
    int tid = threadIdx.x;
    int cnt[8] = {0, 0, 0, 0, 0, 0, 0, 0};
    int s0 = tid * (NSLOT / 256);  // 64 slots per thread, contiguous (stable)
    for (int i = 0; i < NSLOT / 256; i++) cnt[g_route_e[s0 + i]]++;
#pragma unroll
    for (int e = 0; e < 8; e++) hist[tid][e] = cnt[e];
    for (int i = tid; i < MAXTILES; i += 256) g_tile_expert[i] = -1;
    for (int i = tid; i < PADROWS; i += 256) g_bucket_slot[i] = -1;
    __syncthreads();
    if (tid < 8) {
        int s = 0;
        for (int k = 0; k < 256; k++) s += hist[k][tid];
        tot[tid] = s;
    }
    __syncthreads();
    if (tid == 0) {
        int p = 0, tile = 0;
        for (int e = 0; e < 8; e++) {
            base[e] = p;
            int ntile = (tot[e] + 63) >> 6;
            for (int i = 0; i < ntile; i++) {
                g_tile_expert[tile] = e;
                g_tile_rowbase[tile] = p + i * 64;
                tile++;
            }
            p += ntile * 64;
        }
    }
    __syncthreads();
    if (tid < 8) {
        int r = base[tid];
        for (int k = 0; k < 256; k++) { offs[k][tid] = r; r += hist[k][tid]; }
    }
    __syncthreads();
    int o[8];
#pragma unroll
    for (int e = 0; e < 8; e++) o[e] = offs[tid][e];
    for (int i = 0; i < NSLOT / 256; i++) {
        int s = s0 + i;
        int e = g_route_e[s];
        int p = o[e]++;
        g_bucket_slot[p] = s;
        g_pos[s] = p;
    }
}

// ---------------- 3. GEMM1: H = gelu(gather(x) @ w1[e] + b1[e]) ----------------
__global__ __launch_bounds__(256) void gemm1_kernel(
    const float* __restrict__ x, const float* __restrict__ w1,
    const float* __restrict__ b1) {
    int e = g_tile_expert[blockIdx.x];
    if (e < 0) return;
    int rowbase = g_tile_rowbase[blockIdx.x];
    int n0 = blockIdx.y * 64;
    __shared__ float As[16][68];
    __shared__ float Bs[16][64];
    __shared__ int s_tok[64];
    int tid = threadIdx.x;
    if (tid < 64) {
        int slot = g_bucket_slot[rowbase + tid];
        s_tok[tid] = (slot >= 0) ? (slot >> 1) : -1;
    }
    __syncthreads();
    const int a_m = tid >> 2;
    const int a_k = (tid & 3) << 2;
    const int b_k = tid >> 4;
    const int b_n = (tid & 15) << 2;
    const int tx = tid & 15;
    const int ty = tid >> 4;
    const int tok = s_tok[a_m];
    const float* aptr = x + (size_t)(tok < 0 ? 0 : tok) * IN_DIM + a_k;
    const float* bptr = w1 + (size_t)e * IN_DIM * PROJ + (size_t)b_k * PROJ + n0 + b_n;
    float acc[4][4] = {};
    for (int k0 = 0; k0 < IN_DIM; k0 += 16) {
        float4 av = make_float4(0.f, 0.f, 0.f, 0.f);
        if (tok >= 0) av = *(const float4*)(aptr + k0);
        float4 bv = *(const float4*)(bptr + (size_t)k0 * PROJ);
        __syncthreads();
        As[a_k + 0][a_m] = av.x; As[a_k + 1][a_m] = av.y;
        As[a_k + 2][a_m] = av.z; As[a_k + 3][a_m] = av.w;
        *(float4*)&Bs[b_k][b_n] = bv;
        __syncthreads();
#pragma unroll
        for (int kk = 0; kk < 16; kk++) {
            float4 a4 = *(const float4*)&As[kk][ty << 2];
            float4 b4 = *(const float4*)&Bs[kk][tx << 2];
            float ra[4] = {a4.x, a4.y, a4.z, a4.w};
            float rb[4] = {b4.x, b4.y, b4.z, b4.w};
#pragma unroll
            for (int i = 0; i < 4; i++)
#pragma unroll
                for (int j = 0; j < 4; j++) acc[i][j] += ra[i] * rb[j];
        }
    }
    const float* b1e = b1 + (size_t)e * PROJ + n0 + (tx << 2);
    float bb[4] = {b1e[0], b1e[1], b1e[2], b1e[3]};
#pragma unroll
    for (int i = 0; i < 4; i++) {
        size_t r = (size_t)rowbase + (ty << 2) + i;
        float* hrow = g_H + r * PROJ + n0 + (tx << 2);
#pragma unroll
        for (int j = 0; j < 4; j++) hrow[j] = gelu_f(acc[i][j] + bb[j]);
    }
}

// ---------------- 4. GEMM2: Y = w * (H @ w2[e] + b2[e]) ----------------
__global__ __launch_bounds__(256) void gemm2_kernel(
    const float* __restrict__ w2, const float* __restrict__ b2) {
    int e = g_tile_expert[blockIdx.x];
    if (e < 0) return;
    int rowbase = g_tile_rowbase[blockIdx.x];
    int n0 = blockIdx.y * 64;
    __shared__ float As[16][68];
    __shared__ float Bs[16][64];
    __shared__ int s_slot[64];
    int tid = threadIdx.x;
    if (tid < 64) s_slot[tid] = g_bucket_slot[rowbase + tid];
    const int a_m = tid >> 2;
    const int a_k = (tid & 3) << 2;
    const int b_k = tid >> 4;
    const int b_n = (tid & 15) << 2;
    const int tx = tid & 15;
    const int ty = tid >> 4;
    const float* aptr = g_H + (size_t)(rowbase + a_m) * PROJ + a_k;
    const float* bptr = w2 + (size_t)e * PROJ * OUT_DIM + (size_t)b_k * OUT_DIM + n0 + b_n;
    float acc[4][4] = {};
    for (int k0 = 0; k0 < PROJ; k0 += 16) {
        float4 av = *(const float4*)(aptr + k0);
        float4 bv = *(const float4*)(bptr + (size_t)k0 * OUT_DIM);
        __syncthreads();
        As[a_k + 0][a_m] = av.x; As[a_k + 1][a_m] = av.y;
        As[a_k + 2][a_m] = av.z; As[a_k + 3][a_m] = av.w;
        *(float4*)&Bs[b_k][b_n] = bv;
        __syncthreads();
#pragma unroll
        for (int kk = 0; kk < 16; kk++) {
            float4 a4 = *(const float4*)&As[kk][ty << 2];
            float4 b4 = *(const float4*)&Bs[kk][tx << 2];
            float ra[4] = {a4.x, a4.y, a4.z, a4.w};
            float rb[4] = {b4.x, b4.y, b4.z, b4.w};
#pragma unroll
            for (int i = 0; i < 4; i++)
#pragma unroll
                for (int j = 0; j < 4; j++) acc[i][j] += ra[i] * rb[j];
        }
    }
    const float* b2e = b2 + (size_t)e * OUT_DIM + n0 + (tx << 2);
    float bb[4] = {b2e[0], b2e[1], b2e[2], b2e[3]};
#pragma unroll
    for (int i = 0; i < 4; i++) {
        int slot = s_slot[(ty << 2) + i];
        if (slot < 0) continue;
        float w = g_route_w[slot];
        size_t r = (size_t)rowbase + (ty << 2) + i;
        float* yrow = g_Y + r * OUT_DIM + n0 + (tx << 2);
#pragma unroll
        for (int j = 0; j < 4; j++) yrow[j] = w * (acc[i][j] + bb[j]);
    }
}

// ---------------- 5. combine: out[t] = Y[pos(t,0)] + Y[pos(t,1)] ----------------
__global__ __launch_bounds__(256) void combine_kernel(float* __restrict__ out) {
    int idx = blockIdx.x * 256 + threadIdx.x;  // over TT * (OUT_DIM/4)
    int t = idx >> 9;                          // OUT_DIM/4 = 512 per token
    int c = idx & 511;
    int p0 = g_pos[2 * t], p1 = g_pos[2 * t + 1];
    float4 a = ((const float4*)(g_Y + (size_t)p0 * OUT_DIM))[c];
    float4 b = ((const float4*)(g_Y + (size_t)p1 * OUT_DIM))[c];
    ((float4*)out)[idx] = make_float4(a.x + b.x, a.y + b.y, a.z + b.z, a.w + b.w);
}

extern "C" void kernel_launch(void* const* d_in, const int* in_sizes, int n_in,
                              void* d_out, int out_size) {
    const float* x      = (const float*)d_in[0];
    const float* gate_w = (const float*)d_in[1];
    const float* gate_b = (const float*)d_in[2];
    const float* w1     = (const float*)d_in[3];
    const float* b1     = (const float*)d_in[4];
    const float* w2     = (const float*)d_in[5];
    const float* b2     = (const float*)d_in[6];
    float* out = (float*)d_out;

    gating_kernel<<<TT / 8, 256>>>(x, gate_w, gate_b);
    bucket_kernel<<<1, 256>>>();
    gemm1_kernel<<<dim3(MAXTILES, PROJ / 64), 256>>>(x, w1, b1);
    gemm2_kernel<<<dim3(MAXTILES, OUT_DIM / 64), 256>>>(w2, b2);
    combine_kernel<<<(TT * (OUT_DIM / 4)) / 256, 256>>>(out);
}